// round 2
// baseline (speedup 1.0000x reference)
#include <cuda_runtime.h>
#include <cuda_bf16.h>
#include <math.h>

// Problem constants
#define BB   128          // batch
#define TT   512          // seq len
#define INDIM 128
#define HH   1024
#define G3   (3*HH)       // 3072
#define PRED 96
#define MROWS (TT*BB)     // 65536

#define NCOLB 32          // H/32 col blocks
#define NROWB 4           // B/32 row groups

// ---------------------------------------------------------------------------
// Scratch (device globals; allocation-free per harness rules)
// ---------------------------------------------------------------------------
__device__ float g_XT[(size_t)TT * BB * INDIM];   // x transposed [T,B,IN]
__device__ float g_XI[(size_t)TT * BB * G3];      // input-side gate projections [T,B,3H]
__device__ float g_HA[(size_t)TT * BB * HH];      // hidden sequence ping
__device__ float g_HB[(size_t)TT * BB * HH];      // hidden sequence pong

// Row-group barrier state (zero-initialized; gen is monotonic across replays)
__device__ unsigned g_cnt[NROWB];
__device__ unsigned g_gen[NROWB];

// ---------------------------------------------------------------------------
// Kernel: transpose x [B,T,IN] -> [T,B,IN]
// ---------------------------------------------------------------------------
__global__ __launch_bounds__(256) void transpose_x(const float* __restrict__ x,
                                                   float* __restrict__ xt) {
    int idx = blockIdx.x * blockDim.x + threadIdx.x;   // over T*B*IN
    if (idx >= TT * BB * INDIM) return;
    int i = idx % INDIM;
    int r = idx / INDIM;
    int b = r % BB;
    int t = r / BB;
    xt[idx] = x[((size_t)b * TT + t) * INDIM + i];
}

// ---------------------------------------------------------------------------
// Kernel: C[M,N] = A[M,K] @ W[N,K]^T + bias[N]
// 64x64 tile, BK=16, 256 threads, 4x4 microtile.
// ---------------------------------------------------------------------------
__global__ __launch_bounds__(256) void gemm_bias(const float* __restrict__ A,
                                                 const float* __restrict__ W,
                                                 const float* __restrict__ bias,
                                                 float* __restrict__ C,
                                                 int M, int N, int K) {
    const int BK = 16;
    __shared__ float As[BK][68];
    __shared__ float Bs[BK][68];

    int rowBase = blockIdx.y * 64;
    int colBase = blockIdx.x * 64;
    int tid = threadIdx.x;
    int tx = tid & 15;
    int ty = tid >> 4;

    float acc[4][4];
#pragma unroll
    for (int i = 0; i < 4; i++)
#pragma unroll
        for (int j = 0; j < 4; j++) acc[i][j] = 0.f;

    for (int k0 = 0; k0 < K; k0 += BK) {
#pragma unroll
        for (int i = 0; i < 4; i++) {
            int idx = tid + i * 256;
            int r = idx / BK;
            int c = idx % BK;
            As[c][r] = A[(size_t)(rowBase + r) * K + k0 + c];
            Bs[c][r] = W[(size_t)(colBase + r) * K + k0 + c];
        }
        __syncthreads();
#pragma unroll
        for (int kk = 0; kk < BK; kk++) {
            float4 a4 = *reinterpret_cast<const float4*>(&As[kk][ty * 4]);
            float4 b4 = *reinterpret_cast<const float4*>(&Bs[kk][tx * 4]);
            float a[4] = {a4.x, a4.y, a4.z, a4.w};
            float b[4] = {b4.x, b4.y, b4.z, b4.w};
#pragma unroll
            for (int i = 0; i < 4; i++)
#pragma unroll
                for (int j = 0; j < 4; j++) acc[i][j] += a[i] * b[j];
        }
        __syncthreads();
    }

#pragma unroll
    for (int i = 0; i < 4; i++) {
        int row = rowBase + ty * 4 + i;
#pragma unroll
        for (int j = 0; j < 4; j++) {
            int col = colBase + tx * 4 + j;
            C[(size_t)row * N + col] = acc[i][j] + bias[col];
        }
    }
}

// ---------------------------------------------------------------------------
// Row-group grid barrier: syncs the 32 col-blocks of one batch row-group.
// gen is monotonic (works across graph replays); cnt self-resets.
// ---------------------------------------------------------------------------
__device__ __forceinline__ void rowgroup_sync(int rg) {
    __syncthreads();
    if (threadIdx.x == 0) {
        __threadfence();   // make hout writes visible before arriving
        volatile unsigned* genp = &g_gen[rg];
        unsigned my = *genp;
        unsigned prev = atomicAdd(&g_cnt[rg], 1u);
        if (prev == NCOLB - 1) {
            atomicExch(&g_cnt[rg], 0u);
            __threadfence();
            *genp = my + 1;
        } else {
            while (*genp == my) { }
        }
    }
    __syncthreads();
}

// ---------------------------------------------------------------------------
// Persistent per-layer GRU kernel.
// Grid: 128 blocks (32 col-blocks x 4 row-groups), 128 threads.
// Each block owns a 32(batch) x 32(H) tile across all 3 gates and loops over t.
// Microtile 4 rows x 2 cols per gate -> FFMA-bound (smem 40 vs fma 48 cyc/SM/k).
// ---------------------------------------------------------------------------
__global__ __launch_bounds__(128) void gru_layer(const float* __restrict__ XI,   // [T,B,3H]
                                                 const float* __restrict__ Whh,  // [3H,H]
                                                 const float* __restrict__ bhh,  // [3H]
                                                 float* __restrict__ hseq) {     // [T,B,H]
    const int BK = 32;
    __shared__ float As[BK][36];        // [k][m]
    __shared__ float Bs[3][BK][36];     // [g][k][n]

    int bx = blockIdx.x;
    int cb = bx & 31;
    int rg = bx >> 5;
    int colBase = cb * 32;
    int rowBase = rg * 32;
    int tid = threadIdx.x;
    int tx = tid & 15;      // 2 cols each
    int ty = tid >> 4;      // 0..7, 4 rows each

    // Cache biases for my 2 columns (constant across t)
    float br[2], bz[2], bn[2];
#pragma unroll
    for (int j = 0; j < 2; j++) {
        int col = colBase + tx * 2 + j;
        br[j] = bhh[col];
        bz[j] = bhh[HH + col];
        bn[j] = bhh[2 * HH + col];
    }

    for (int t = 0; t < TT; t++) {
        const float* hprev = hseq + (size_t)(t - 1) * BB * HH;  // invalid at t=0, guarded
        const float* xi_t = XI + (size_t)t * BB * G3;
        float* hout = hseq + (size_t)t * BB * HH;

        float acc[3][4][2];
#pragma unroll
        for (int g = 0; g < 3; g++)
#pragma unroll
            for (int i = 0; i < 4; i++)
#pragma unroll
                for (int j = 0; j < 2; j++) acc[g][i][j] = 0.f;

        for (int k0 = 0; k0 < HH; k0 += BK) {
            // Load As: 32x32 hprev tile (1024 floats = 256 float4, 2 per thread)
#pragma unroll
            for (int i = 0; i < 2; i++) {
                int e = tid + i * 128;
                int r = e >> 3;
                int c4 = e & 7;
                float4 v;
                if (t == 0) { v.x = v.y = v.z = v.w = 0.f; }
                else v = *reinterpret_cast<const float4*>(
                         &hprev[(size_t)(rowBase + r) * HH + k0 + c4 * 4]);
                As[c4 * 4 + 0][r] = v.x;
                As[c4 * 4 + 1][r] = v.y;
                As[c4 * 4 + 2][r] = v.z;
                As[c4 * 4 + 3][r] = v.w;
            }
            // Load Bs: 3 gates x 32x32 Whh tiles
#pragma unroll
            for (int g = 0; g < 3; g++) {
#pragma unroll
                for (int i = 0; i < 2; i++) {
                    int e = tid + i * 128;
                    int r = e >> 3;
                    int c4 = e & 7;
                    float4 v = *reinterpret_cast<const float4*>(
                        &Whh[(size_t)(g * HH + colBase + r) * HH + k0 + c4 * 4]);
                    Bs[g][c4 * 4 + 0][r] = v.x;
                    Bs[g][c4 * 4 + 1][r] = v.y;
                    Bs[g][c4 * 4 + 2][r] = v.z;
                    Bs[g][c4 * 4 + 3][r] = v.w;
                }
            }
            __syncthreads();
#pragma unroll
            for (int kk = 0; kk < BK; kk++) {
                float4 a4 = *reinterpret_cast<const float4*>(&As[kk][ty * 4]);
                float a[4] = {a4.x, a4.y, a4.z, a4.w};
#pragma unroll
                for (int g = 0; g < 3; g++) {
                    float2 b2 = *reinterpret_cast<const float2*>(&Bs[g][kk][tx * 2]);
#pragma unroll
                    for (int i = 0; i < 4; i++) {
                        acc[g][i][0] += a[i] * b2.x;
                        acc[g][i][1] += a[i] * b2.y;
                    }
                }
            }
            __syncthreads();
        }

        // Epilogue: gate fusion
#pragma unroll
        for (int i = 0; i < 4; i++) {
            int row = rowBase + ty * 4 + i;
            const float* xi = xi_t + (size_t)row * G3;
            float2 hv;
#pragma unroll
            for (int j = 0; j < 2; j++) {
                int col = colBase + tx * 2 + j;
                float hr = acc[0][i][j] + br[j];
                float hz = acc[1][i][j] + bz[j];
                float hn = acc[2][i][j] + bn[j];
                float xr = xi[col];
                float xz = xi[HH + col];
                float xn = xi[2 * HH + col];
                float r = 1.f / (1.f + __expf(-(xr + hr)));
                float z = 1.f / (1.f + __expf(-(xz + hz)));
                float n = tanhf(xn + r * hn);
                float hp = (t == 0) ? 0.f : hprev[(size_t)row * HH + col];
                float h = (1.f - z) * n + z * hp;
                if (j == 0) hv.x = h; else hv.y = h;
            }
            *reinterpret_cast<float2*>(&hout[(size_t)row * HH + colBase + tx * 2]) = hv;
        }

        // Make step t visible to all col-blocks of this row group before t+1
        if (t < TT - 1) rowgroup_sync(rg);
    }
}

// ---------------------------------------------------------------------------
// Kernel: FC head. out[b,p] = last[b,:] . fc_w[p,:] + fc_b[p]
// ---------------------------------------------------------------------------
__global__ __launch_bounds__(256) void fc_kernel(const float* __restrict__ last,
                                                 const float* __restrict__ fcw,
                                                 const float* __restrict__ fcb,
                                                 float* __restrict__ out) {
    int warp = (blockIdx.x * blockDim.x + threadIdx.x) >> 5;
    int lane = threadIdx.x & 31;
    if (warp >= BB * PRED) return;
    int b = warp / PRED;
    int p = warp % PRED;
    float s = 0.f;
    const float* lrow = last + (size_t)b * HH;
    const float* wrow = fcw + (size_t)p * HH;
    for (int k = lane; k < HH; k += 32) s += lrow[k] * wrow[k];
#pragma unroll
    for (int off = 16; off; off >>= 1) s += __shfl_xor_sync(0xFFFFFFFFu, s, off);
    if (lane == 0) out[b * PRED + p] = s + fcb[p];
}

// ---------------------------------------------------------------------------
// Launcher: 8 graph nodes total (transpose, 3x gemm, 3x persistent layer, fc)
// ---------------------------------------------------------------------------
extern "C" void kernel_launch(void* const* d_in, const int* in_sizes, int n_in,
                              void* d_out, int out_size) {
    const float* x = (const float*)d_in[0];
    const float* w_ih[3] = {(const float*)d_in[1], (const float*)d_in[5], (const float*)d_in[9]};
    const float* w_hh[3] = {(const float*)d_in[2], (const float*)d_in[6], (const float*)d_in[10]};
    const float* b_ih[3] = {(const float*)d_in[3], (const float*)d_in[7], (const float*)d_in[11]};
    const float* b_hh[3] = {(const float*)d_in[4], (const float*)d_in[8], (const float*)d_in[12]};
    const float* fcw = (const float*)d_in[13];
    const float* fcb = (const float*)d_in[14];
    float* out = (float*)d_out;

    float *XT, *XI, *HA, *HB;
    cudaGetSymbolAddress((void**)&XT, g_XT);
    cudaGetSymbolAddress((void**)&XI, g_XI);
    cudaGetSymbolAddress((void**)&HA, g_HA);
    cudaGetSymbolAddress((void**)&HB, g_HB);

    // 1) transpose x to [T,B,IN]
    {
        int total = TT * BB * INDIM;
        transpose_x<<<(total + 255) / 256, 256>>>(x, XT);
    }

    const float* layin = XT;
    int Kin = INDIM;
    float* seqbuf[3] = {HA, HB, HA};

    for (int l = 0; l < 3; l++) {
        // 2) xi = layin @ w_ih^T + b_ih   (whole sequence at once)
        dim3 ggrid(G3 / 64, MROWS / 64);
        gemm_bias<<<ggrid, 256>>>(layin, w_ih[l], b_ih[l], XI, MROWS, G3, Kin);

        // 3) persistent recurrent kernel for all 512 steps
        gru_layer<<<NCOLB * NROWB, 128>>>(XI, w_hh[l], b_hh[l], seqbuf[l]);

        layin = seqbuf[l];
        Kin = HH;
    }

    // 4) FC head on h[T-1] of last layer
    {
        const float* last = seqbuf[2] + (size_t)(TT - 1) * BB * HH;
        int warps = BB * PRED;
        int blocks = (warps * 32 + 255) / 256;
        fc_kernel<<<blocks, 256>>>(last, fcw, fcb, out);
    }
}

// round 5
// speedup vs baseline: 2.6686x; 2.6686x over previous
#include <cuda_runtime.h>
#include <cuda_bf16.h>
#include <math.h>
#include <stdint.h>

// Problem constants
#define BB   128
#define TT   512
#define INDIM 128
#define HH   1024
#define G3   (3*HH)
#define PRED 96
#define MROWS (TT*BB)

#define NCOLB 32          // H/32 col blocks
#define NROWB 4           // B/32 row groups

// ---------------------------------------------------------------------------
// Scratch
// ---------------------------------------------------------------------------
__device__ float g_XT[(size_t)TT * BB * INDIM];
__device__ float g_XI[(size_t)TT * BB * G3];
__device__ float g_HA[(size_t)TT * BB * HH];
__device__ float g_HB[(size_t)TT * BB * HH];

__device__ unsigned g_cnt[NROWB];
__device__ unsigned g_gen[NROWB];

// ---------------------------------------------------------------------------
// PTX helpers
// ---------------------------------------------------------------------------
__device__ __forceinline__ void mma_tf32(float c[4], const uint32_t a[4], const uint32_t b[2]) {
    asm volatile(
        "mma.sync.aligned.m16n8k8.row.col.f32.tf32.tf32.f32 "
        "{%0,%1,%2,%3}, {%4,%5,%6,%7}, {%8,%9}, {%0,%1,%2,%3};\n"
        : "+f"(c[0]), "+f"(c[1]), "+f"(c[2]), "+f"(c[3])
        : "r"(a[0]), "r"(a[1]), "r"(a[2]), "r"(a[3]), "r"(b[0]), "r"(b[1]));
}
__device__ __forceinline__ uint32_t f2tf32(uint32_t x) {
    uint32_t y;
    asm volatile("cvt.rna.tf32.f32 %0, %1;" : "=r"(y) : "r"(x));
    return y;
}
__device__ __forceinline__ void cp16(uint32_t saddr, const void* g) {
    asm volatile("cp.async.cg.shared.global [%0], [%1], 16;" :: "r"(saddr), "l"(g));
}
__device__ __forceinline__ void cp_commit() { asm volatile("cp.async.commit_group;"); }
__device__ __forceinline__ void cp_wait1() { asm volatile("cp.async.wait_group 1;"); }

// ---------------------------------------------------------------------------
// transpose x [B,T,IN] -> [T,B,IN]
// ---------------------------------------------------------------------------
__global__ __launch_bounds__(256) void transpose_x(const float* __restrict__ x,
                                                   float* __restrict__ xt) {
    int idx = blockIdx.x * blockDim.x + threadIdx.x;
    if (idx >= TT * BB * INDIM) return;
    int i = idx % INDIM;
    int r = idx / INDIM;
    int b = r % BB;
    int t = r / BB;
    xt[idx] = x[((size_t)b * TT + t) * INDIM + i];
}

// ---------------------------------------------------------------------------
// tf32 mma GEMM: C[M,N] = A[M,K] @ W[N,K]^T + bias[N]
// Block tile 128x64, BK=32, 256 threads (8 warps, warp tile 32x32).
// Static smem ~27.6 KB.
// ---------------------------------------------------------------------------
#define GP 36   // padded row stride (words) -> conflict-free fragment LDS
__global__ __launch_bounds__(256) void gemm_mma(const float* __restrict__ A,
                                                const float* __restrict__ W,
                                                const float* __restrict__ bias,
                                                float* __restrict__ C,
                                                int M, int N, int K) {
    __shared__ uint32_t As[128 * GP];
    __shared__ uint32_t Bs[64 * GP];

    int tid = threadIdx.x;
    int warp = tid >> 5, lane = tid & 31;
    int gid = lane >> 2, tig = lane & 3;
    int wm = warp & 3, wn = warp >> 2;
    int rowBase = blockIdx.y * 128;
    int colBase = blockIdx.x * 64;

    float acc[2][4][4];
#pragma unroll
    for (int mt = 0; mt < 2; mt++)
#pragma unroll
        for (int nt = 0; nt < 4; nt++)
#pragma unroll
            for (int k = 0; k < 4; k++) acc[mt][nt][k] = 0.f;

    for (int k0 = 0; k0 < K; k0 += 32) {
#pragma unroll
        for (int i = 0; i < 4; i++) {
            int f4 = tid + i * 256;
            int r = f4 >> 3, c4 = f4 & 7;
            uint4 v = *reinterpret_cast<const uint4*>(&A[(size_t)(rowBase + r) * K + k0 + c4 * 4]);
            *reinterpret_cast<uint4*>(&As[r * GP + c4 * 4]) = v;
        }
#pragma unroll
        for (int i = 0; i < 2; i++) {
            int f4 = tid + i * 256;
            int r = f4 >> 3, c4 = f4 & 7;
            uint4 v = *reinterpret_cast<const uint4*>(&W[(size_t)(colBase + r) * K + k0 + c4 * 4]);
            *reinterpret_cast<uint4*>(&Bs[r * GP + c4 * 4]) = v;
        }
        __syncthreads();
#pragma unroll
        for (int ks = 0; ks < 4; ks++) {
            int kk = ks * 8;
            uint32_t a[2][4];
#pragma unroll
            for (int mt = 0; mt < 2; mt++) {
                int r0 = wm * 32 + mt * 16 + gid;
                a[mt][0] = f2tf32(As[r0 * GP + kk + tig]);
                a[mt][1] = f2tf32(As[(r0 + 8) * GP + kk + tig]);
                a[mt][2] = f2tf32(As[r0 * GP + kk + tig + 4]);
                a[mt][3] = f2tf32(As[(r0 + 8) * GP + kk + tig + 4]);
            }
#pragma unroll
            for (int nt = 0; nt < 4; nt++) {
                int n0 = wn * 32 + nt * 8 + gid;
                uint32_t b[2] = {f2tf32(Bs[n0 * GP + kk + tig]),
                                 f2tf32(Bs[n0 * GP + kk + tig + 4])};
#pragma unroll
                for (int mt = 0; mt < 2; mt++) mma_tf32(acc[mt][nt], a[mt], b);
            }
        }
        __syncthreads();
    }

#pragma unroll
    for (int mt = 0; mt < 2; mt++) {
        int row = rowBase + wm * 32 + mt * 16 + gid;
#pragma unroll
        for (int nt = 0; nt < 4; nt++) {
            int col = colBase + wn * 32 + nt * 8 + 2 * tig;
            float2 bi = *reinterpret_cast<const float2*>(&bias[col]);
            float2 v0 = {acc[mt][nt][0] + bi.x, acc[mt][nt][1] + bi.y};
            float2 v1 = {acc[mt][nt][2] + bi.x, acc[mt][nt][3] + bi.y};
            *reinterpret_cast<float2*>(&C[(size_t)row * N + col]) = v0;
            *reinterpret_cast<float2*>(&C[(size_t)(row + 8) * N + col]) = v1;
        }
    }
}

// ---------------------------------------------------------------------------
// Row-group grid barrier (proven in round 2)
// ---------------------------------------------------------------------------
__device__ __forceinline__ void rowgroup_sync(int rg) {
    __syncthreads();
    if (threadIdx.x == 0) {
        __threadfence();
        volatile unsigned* genp = &g_gen[rg];
        unsigned my = *genp;
        unsigned prev = atomicAdd(&g_cnt[rg], 1u);
        if (prev == NCOLB - 1) {
            atomicExch(&g_cnt[rg], 0u);
            __threadfence();
            *genp = my + 1;
        } else {
            while (*genp == my) { __nanosleep(32); }
        }
    }
    __syncthreads();
}

// ---------------------------------------------------------------------------
// Persistent per-layer GRU kernel (tf32 mma + 2-stage cp.async, STATIC smem).
// Grid: 128 blocks (32 col x 4 rowgroups), 128 threads (4 warps).
// Block tile: 32 batch rows x 32 H-cols x 3 gates.
// Warp w owns H-cols [w*8, w*8+8) for ALL 3 gates -> gate fusion in registers,
// no cross-warp exchange buffer.
// Static smem: sA 2x32x36 + sB 2x96x36 = 36 KB.
// ---------------------------------------------------------------------------
#define SA_W (32 * GP)   // 1152 words per stage
#define SB_W (96 * GP)   // 3456 words per stage

__global__ __launch_bounds__(128) void gru_layer(const float* __restrict__ XI,   // [T,B,3H]
                                                 const float* __restrict__ Whh,  // [3H,H]
                                                 const float* __restrict__ bhh,  // [3H]
                                                 float* __restrict__ hseq) {     // [T,B,H]
    __shared__ uint32_t sA[2 * SA_W];
    __shared__ uint32_t sB[2 * SB_W];

    int tid = threadIdx.x;
    int warp = tid >> 5, lane = tid & 31;
    int gid = lane >> 2, tig = lane & 3;
    int bx = blockIdx.x;
    int cb = bx & 31, rg = bx >> 5;
    int colBase = cb * 32;
    int rowBase = rg * 32;

    uint32_t sA_base = (uint32_t)__cvta_generic_to_shared(sA);
    uint32_t sB_base = (uint32_t)__cvta_generic_to_shared(sB);

    // This thread's two output columns (same for every gate)
    int col0 = colBase + warp * 8 + 2 * tig;
    float2 ebr = *reinterpret_cast<const float2*>(&bhh[col0]);
    float2 ebz = *reinterpret_cast<const float2*>(&bhh[HH + col0]);
    float2 ebn = *reinterpret_cast<const float2*>(&bhh[2 * HH + col0]);

    for (int t = 0; t < TT; t++) {
        const float* hprev = hseq + (size_t)(t - 1) * BB * HH;  // deref only when t>0
        const float* xi_t = XI + (size_t)t * BB * G3;
        float* hout = hseq + (size_t)t * BB * HH;

        float acc[2][3][4];
#pragma unroll
        for (int mt = 0; mt < 2; mt++)
#pragma unroll
            for (int g = 0; g < 3; g++)
#pragma unroll
                for (int k = 0; k < 4; k++) acc[mt][g][k] = 0.f;

        if (t > 0) {
            // prologue: chunk 0 -> stage 0
            {
#pragma unroll
                for (int i = 0; i < 2; i++) {
                    int f4 = tid + i * 128;
                    int r = f4 >> 3, c4 = f4 & 7;
                    cp16(sA_base + (r * GP + c4 * 4) * 4,
                         &hprev[(size_t)(rowBase + r) * HH + c4 * 4]);
                }
#pragma unroll
                for (int i = 0; i < 6; i++) {
                    int f4 = tid + i * 128;
                    int row96 = f4 >> 3, c4 = f4 & 7;
                    int g = row96 >> 5, rr = row96 & 31;
                    cp16(sB_base + (row96 * GP + c4 * 4) * 4,
                         &Whh[(size_t)(g * HH + colBase + rr) * HH + c4 * 4]);
                }
                cp_commit();
            }

            for (int c = 0; c < 32; c++) {
                // prefetch chunk c+1 into the other stage
                if (c + 1 < 32) {
                    int k0 = (c + 1) * 32;
                    int st = (c + 1) & 1;
#pragma unroll
                    for (int i = 0; i < 2; i++) {
                        int f4 = tid + i * 128;
                        int r = f4 >> 3, c4 = f4 & 7;
                        cp16(sA_base + (st * SA_W + r * GP + c4 * 4) * 4,
                             &hprev[(size_t)(rowBase + r) * HH + k0 + c4 * 4]);
                    }
#pragma unroll
                    for (int i = 0; i < 6; i++) {
                        int f4 = tid + i * 128;
                        int row96 = f4 >> 3, c4 = f4 & 7;
                        int g = row96 >> 5, rr = row96 & 31;
                        cp16(sB_base + (st * SB_W + row96 * GP + c4 * 4) * 4,
                             &Whh[(size_t)(g * HH + colBase + rr) * HH + k0 + c4 * 4]);
                    }
                }
                cp_commit();
                cp_wait1();          // chunk c's group retired (this thread)
                __syncthreads();     // all threads' chunk c data visible

                const uint32_t* cA = sA + (c & 1) * SA_W;
                const uint32_t* cB = sB + (c & 1) * SB_W;
#pragma unroll
                for (int ks = 0; ks < 4; ks++) {
                    int kk = ks * 8;
                    uint32_t a[2][4];
#pragma unroll
                    for (int mt = 0; mt < 2; mt++) {
                        int r0 = mt * 16 + gid;
                        a[mt][0] = f2tf32(cA[r0 * GP + kk + tig]);
                        a[mt][1] = f2tf32(cA[(r0 + 8) * GP + kk + tig]);
                        a[mt][2] = f2tf32(cA[r0 * GP + kk + tig + 4]);
                        a[mt][3] = f2tf32(cA[(r0 + 8) * GP + kk + tig + 4]);
                    }
#pragma unroll
                    for (int g = 0; g < 3; g++) {
                        int nrow = g * 32 + warp * 8 + gid;
                        uint32_t b[2] = {f2tf32(cB[nrow * GP + kk + tig]),
                                         f2tf32(cB[nrow * GP + kk + tig + 4])};
#pragma unroll
                        for (int mt = 0; mt < 2; mt++) mma_tf32(acc[mt][g], a[mt], b);
                    }
                }
                __syncthreads();     // stage (c&1) fully read before overwrite with c+2
            }
        }

        // Gate fusion in registers: thread owns rows {mt*16+gid, +8}, cols {col0, col0+1}
#pragma unroll
        for (int mt = 0; mt < 2; mt++) {
#pragma unroll
            for (int kp = 0; kp < 2; kp++) {
                int grow = rowBase + mt * 16 + gid + kp * 8;
                const float* xi = xi_t + (size_t)grow * G3 + col0;
                float2 xr = *reinterpret_cast<const float2*>(xi);
                float2 xz = *reinterpret_cast<const float2*>(xi + HH);
                float2 xn = *reinterpret_cast<const float2*>(xi + 2 * HH);
                float2 hp = {0.f, 0.f};
                if (t > 0)
                    hp = *reinterpret_cast<const float2*>(&hprev[(size_t)grow * HH + col0]);

                float rv0 = acc[mt][0][kp * 2], rv1 = acc[mt][0][kp * 2 + 1];
                float zv0 = acc[mt][1][kp * 2], zv1 = acc[mt][1][kp * 2 + 1];
                float nv0 = acc[mt][2][kp * 2], nv1 = acc[mt][2][kp * 2 + 1];

                float r0 = 1.f / (1.f + __expf(-(xr.x + rv0 + ebr.x)));
                float r1 = 1.f / (1.f + __expf(-(xr.y + rv1 + ebr.y)));
                float z0 = 1.f / (1.f + __expf(-(xz.x + zv0 + ebz.x)));
                float z1 = 1.f / (1.f + __expf(-(xz.y + zv1 + ebz.y)));
                float n0 = tanhf(xn.x + r0 * (nv0 + ebn.x));
                float n1 = tanhf(xn.y + r1 * (nv1 + ebn.y));
                float2 hv = {(1.f - z0) * n0 + z0 * hp.x,
                             (1.f - z1) * n1 + z1 * hp.y};
                *reinterpret_cast<float2*>(&hout[(size_t)grow * HH + col0]) = hv;
            }
        }

        if (t < TT - 1) rowgroup_sync(rg);
    }
}

// ---------------------------------------------------------------------------
// FC head
// ---------------------------------------------------------------------------
__global__ __launch_bounds__(256) void fc_kernel(const float* __restrict__ last,
                                                 const float* __restrict__ fcw,
                                                 const float* __restrict__ fcb,
                                                 float* __restrict__ out) {
    int warp = (blockIdx.x * blockDim.x + threadIdx.x) >> 5;
    int lane = threadIdx.x & 31;
    if (warp >= BB * PRED) return;
    int b = warp / PRED;
    int p = warp % PRED;
    float s = 0.f;
    const float* lrow = last + (size_t)b * HH;
    const float* wrow = fcw + (size_t)p * HH;
    for (int k = lane; k < HH; k += 32) s += lrow[k] * wrow[k];
#pragma unroll
    for (int off = 16; off; off >>= 1) s += __shfl_xor_sync(0xFFFFFFFFu, s, off);
    if (lane == 0) out[b * PRED + p] = s + fcb[p];
}

// ---------------------------------------------------------------------------
// Launcher: 8 graph nodes, no attribute calls, no dynamic smem
// ---------------------------------------------------------------------------
extern "C" void kernel_launch(void* const* d_in, const int* in_sizes, int n_in,
                              void* d_out, int out_size) {
    const float* x = (const float*)d_in[0];
    const float* w_ih[3] = {(const float*)d_in[1], (const float*)d_in[5], (const float*)d_in[9]};
    const float* w_hh[3] = {(const float*)d_in[2], (const float*)d_in[6], (const float*)d_in[10]};
    const float* b_ih[3] = {(const float*)d_in[3], (const float*)d_in[7], (const float*)d_in[11]};
    const float* b_hh[3] = {(const float*)d_in[4], (const float*)d_in[8], (const float*)d_in[12]};
    const float* fcw = (const float*)d_in[13];
    const float* fcb = (const float*)d_in[14];
    float* out = (float*)d_out;

    float *XT, *XI, *HA, *HB;
    cudaGetSymbolAddress((void**)&XT, g_XT);
    cudaGetSymbolAddress((void**)&XI, g_XI);
    cudaGetSymbolAddress((void**)&HA, g_HA);
    cudaGetSymbolAddress((void**)&HB, g_HB);

    {
        int total = TT * BB * INDIM;
        transpose_x<<<(total + 255) / 256, 256>>>(x, XT);
    }

    const float* layin = XT;
    int Kin = INDIM;
    float* seqbuf[3] = {HA, HB, HA};

    for (int l = 0; l < 3; l++) {
        dim3 ggrid(G3 / 64, MROWS / 128);
        gemm_mma<<<ggrid, 256>>>(layin, w_ih[l], b_ih[l], XI, MROWS, G3, Kin);

        gru_layer<<<NCOLB * NROWB, 128>>>(XI, w_hh[l], b_hh[l], seqbuf[l]);

        layin = seqbuf[l];
        Kin = HH;
    }

    {
        const float* last = seqbuf[2] + (size_t)(TT - 1) * BB * HH;
        int warps = BB * PRED;
        int blocks = (warps * 32 + 255) / 256;
        fc_kernel<<<blocks, 256>>>(last, fcw, fcb, out);
    }
}

// round 6
// speedup vs baseline: 2.7297x; 1.0229x over previous
#include <cuda_runtime.h>
#include <cuda_bf16.h>
#include <math.h>
#include <stdint.h>

// Problem constants
#define BB   128
#define TT   512
#define INDIM 128
#define HH   1024
#define G3   (3*HH)
#define PRED 96
#define MROWS (TT*BB)

#define NCOLB 32          // H/32 col blocks
#define NROWB 4           // B/32 row groups

// ---------------------------------------------------------------------------
// Scratch
// ---------------------------------------------------------------------------
__device__ float g_XT[(size_t)TT * BB * INDIM];
__device__ float g_XI[(size_t)TT * BB * G3];
__device__ float g_HA[(size_t)TT * BB * HH];
__device__ float g_HB[(size_t)TT * BB * HH];
__device__ uint32_t g_WIH[3][(size_t)G3 * HH];   // tf32-rounded weights
__device__ uint32_t g_WHH[3][(size_t)G3 * HH];

__device__ unsigned g_cnt[NROWB];
__device__ unsigned g_gen[NROWB];

// ---------------------------------------------------------------------------
// PTX helpers
// ---------------------------------------------------------------------------
__device__ __forceinline__ void mma_tf32(float c[4], const uint32_t a[4], const uint32_t b[2]) {
    asm volatile(
        "mma.sync.aligned.m16n8k8.row.col.f32.tf32.tf32.f32 "
        "{%0,%1,%2,%3}, {%4,%5,%6,%7}, {%8,%9}, {%0,%1,%2,%3};\n"
        : "+f"(c[0]), "+f"(c[1]), "+f"(c[2]), "+f"(c[3])
        : "r"(a[0]), "r"(a[1]), "r"(a[2]), "r"(a[3]), "r"(b[0]), "r"(b[1]));
}
__device__ __forceinline__ uint32_t f2tf32(uint32_t x) {
    uint32_t y;
    asm volatile("cvt.rna.tf32.f32 %0, %1;" : "=r"(y) : "r"(x));
    return y;
}
__device__ __forceinline__ void cp16(uint32_t saddr, const void* g) {
    asm volatile("cp.async.cg.shared.global [%0], [%1], 16;" :: "r"(saddr), "l"(g) : "memory");
}
__device__ __forceinline__ void cp_commit() { asm volatile("cp.async.commit_group;" ::: "memory"); }
__device__ __forceinline__ void cp_wait1() { asm volatile("cp.async.wait_group 1;" ::: "memory"); }
__device__ __forceinline__ void cp_wait0() { asm volatile("cp.async.wait_group 0;" ::: "memory"); }

// ---------------------------------------------------------------------------
// transpose x [B,T,IN] -> [T,B,IN]
// ---------------------------------------------------------------------------
__global__ __launch_bounds__(256) void transpose_x(const float* __restrict__ x,
                                                   float* __restrict__ xt) {
    int idx = blockIdx.x * blockDim.x + threadIdx.x;
    if (idx >= TT * BB * INDIM) return;
    int i = idx % INDIM;
    int r = idx / INDIM;
    int b = r % BB;
    int t = r / BB;
    xt[idx] = x[((size_t)b * TT + t) * INDIM + i];
}

// ---------------------------------------------------------------------------
// prep: round all 6 weight matrices to tf32 (one float4 per thread)
// ---------------------------------------------------------------------------
#define S0F4 (G3 * INDIM / 4)      // 98304  (wih0)
#define S1F4 (G3 * HH / 4)         // 786432 (each of the other 5)
#define PREP_F4 (S0F4 + 5 * S1F4)  // 4030464 = 15744 * 256

__global__ __launch_bounds__(256) void prep_weights(
    const float* __restrict__ wih0, const float* __restrict__ whh0,
    const float* __restrict__ wih1, const float* __restrict__ whh1,
    const float* __restrict__ wih2, const float* __restrict__ whh2,
    uint32_t* __restrict__ dwih0, uint32_t* __restrict__ dwhh0,
    uint32_t* __restrict__ dwih1, uint32_t* __restrict__ dwhh1,
    uint32_t* __restrict__ dwih2, uint32_t* __restrict__ dwhh2) {
    long idx = (long)blockIdx.x * 256 + threadIdx.x;   // float4 index
    if (idx >= PREP_F4) return;
    const float* src;
    uint32_t* dst;
    long off;
    if (idx < S0F4) { src = wih0; dst = dwih0; off = idx; }
    else {
        long r = idx - S0F4;
        int seg = (int)(r / S1F4);
        off = r % S1F4;
        switch (seg) {
            case 0: src = whh0; dst = dwhh0; break;
            case 1: src = wih1; dst = dwih1; break;
            case 2: src = whh1; dst = dwhh1; break;
            case 3: src = wih2; dst = dwih2; break;
            default: src = whh2; dst = dwhh2; break;
        }
    }
    uint4 v = *reinterpret_cast<const uint4*>(src + off * 4);
    v.x = f2tf32(v.x); v.y = f2tf32(v.y); v.z = f2tf32(v.z); v.w = f2tf32(v.w);
    *reinterpret_cast<uint4*>(dst + off * 4) = v;
}

// ---------------------------------------------------------------------------
// tf32 mma GEMM: C[M,N] = A[M,K] @ Wt[N,K]^T + bias[N]
// Wt pre-rounded tf32. A rounded at smem-store. Register double-buffering.
// Block tile 128x64, BK=32, 256 threads (8 warps, warp tile 32x32).
// ---------------------------------------------------------------------------
#define GP 36   // padded row stride (words)
__global__ __launch_bounds__(256) void gemm_mma(const float* __restrict__ A,
                                                const uint32_t* __restrict__ Wt,
                                                const float* __restrict__ bias,
                                                float* __restrict__ C,
                                                int M, int N, int K) {
    __shared__ uint32_t As[128 * GP];
    __shared__ uint32_t Bs[64 * GP];

    int tid = threadIdx.x;
    int warp = tid >> 5, lane = tid & 31;
    int gid = lane >> 2, tig = lane & 3;
    int wm = warp & 3, wn = warp >> 2;
    int rowBase = blockIdx.y * 128;
    int colBase = blockIdx.x * 64;

    // copy indices
    int ra[4], ca[4], rb[2], cb2[2];
#pragma unroll
    for (int i = 0; i < 4; i++) { int f4 = tid + i * 256; ra[i] = f4 >> 3; ca[i] = f4 & 7; }
#pragma unroll
    for (int i = 0; i < 2; i++) { int f4 = tid + i * 256; rb[i] = f4 >> 3; cb2[i] = f4 & 7; }

    float acc[2][4][4];
#pragma unroll
    for (int mt = 0; mt < 2; mt++)
#pragma unroll
        for (int nt = 0; nt < 4; nt++)
#pragma unroll
            for (int k = 0; k < 4; k++) acc[mt][nt][k] = 0.f;

    // prologue: load chunk 0 to regs, store to smem
    uint4 pa[4], pb[2];
#pragma unroll
    for (int i = 0; i < 4; i++)
        pa[i] = *reinterpret_cast<const uint4*>(&A[(size_t)(rowBase + ra[i]) * K + ca[i] * 4]);
#pragma unroll
    for (int i = 0; i < 2; i++)
        pb[i] = *reinterpret_cast<const uint4*>(&Wt[(size_t)(colBase + rb[i]) * K + cb2[i] * 4]);
#pragma unroll
    for (int i = 0; i < 4; i++) {
        uint4 v = pa[i];
        v.x = f2tf32(v.x); v.y = f2tf32(v.y); v.z = f2tf32(v.z); v.w = f2tf32(v.w);
        *reinterpret_cast<uint4*>(&As[ra[i] * GP + ca[i] * 4]) = v;
    }
#pragma unroll
    for (int i = 0; i < 2; i++)
        *reinterpret_cast<uint4*>(&Bs[rb[i] * GP + cb2[i] * 4]) = pb[i];
    __syncthreads();

    for (int k0 = 0; k0 < K; k0 += 32) {
        bool has_next = (k0 + 32 < K);
        if (has_next) {
#pragma unroll
            for (int i = 0; i < 4; i++)
                pa[i] = *reinterpret_cast<const uint4*>(&A[(size_t)(rowBase + ra[i]) * K + k0 + 32 + ca[i] * 4]);
#pragma unroll
            for (int i = 0; i < 2; i++)
                pb[i] = *reinterpret_cast<const uint4*>(&Wt[(size_t)(colBase + rb[i]) * K + k0 + 32 + cb2[i] * 4]);
        }
#pragma unroll
        for (int ks = 0; ks < 4; ks++) {
            int kk = ks * 8;
            uint32_t a[2][4];
#pragma unroll
            for (int mt = 0; mt < 2; mt++) {
                int r0 = wm * 32 + mt * 16 + gid;
                a[mt][0] = As[r0 * GP + kk + tig];
                a[mt][1] = As[(r0 + 8) * GP + kk + tig];
                a[mt][2] = As[r0 * GP + kk + tig + 4];
                a[mt][3] = As[(r0 + 8) * GP + kk + tig + 4];
            }
#pragma unroll
            for (int nt = 0; nt < 4; nt++) {
                int n0 = wn * 32 + nt * 8 + gid;
                uint32_t b[2] = {Bs[n0 * GP + kk + tig], Bs[n0 * GP + kk + tig + 4]};
#pragma unroll
                for (int mt = 0; mt < 2; mt++) mma_tf32(acc[mt][nt], a[mt], b);
            }
        }
        __syncthreads();
        if (has_next) {
#pragma unroll
            for (int i = 0; i < 4; i++) {
                uint4 v = pa[i];
                v.x = f2tf32(v.x); v.y = f2tf32(v.y); v.z = f2tf32(v.z); v.w = f2tf32(v.w);
                *reinterpret_cast<uint4*>(&As[ra[i] * GP + ca[i] * 4]) = v;
            }
#pragma unroll
            for (int i = 0; i < 2; i++)
                *reinterpret_cast<uint4*>(&Bs[rb[i] * GP + cb2[i] * 4]) = pb[i];
            __syncthreads();
        }
    }

#pragma unroll
    for (int mt = 0; mt < 2; mt++) {
        int row = rowBase + wm * 32 + mt * 16 + gid;
#pragma unroll
        for (int nt = 0; nt < 4; nt++) {
            int col = colBase + wn * 32 + nt * 8 + 2 * tig;
            float2 bi = *reinterpret_cast<const float2*>(&bias[col]);
            float2 v0 = {acc[mt][nt][0] + bi.x, acc[mt][nt][1] + bi.y};
            float2 v1 = {acc[mt][nt][2] + bi.x, acc[mt][nt][3] + bi.y};
            *reinterpret_cast<float2*>(&C[(size_t)row * N + col]) = v0;
            *reinterpret_cast<float2*>(&C[(size_t)(row + 8) * N + col]) = v1;
        }
    }
}

// ---------------------------------------------------------------------------
// Row-group grid barrier
// ---------------------------------------------------------------------------
__device__ __forceinline__ void rowgroup_sync(int rg) {
    __syncthreads();
    if (threadIdx.x == 0) {
        __threadfence();
        volatile unsigned* genp = &g_gen[rg];
        unsigned my = *genp;
        unsigned prev = atomicAdd(&g_cnt[rg], 1u);
        if (prev == NCOLB - 1) {
            atomicExch(&g_cnt[rg], 0u);
            __threadfence();
            *genp = my + 1;
        } else {
            while (*genp == my) { __nanosleep(32); }
        }
    }
    __syncthreads();
}

// ---------------------------------------------------------------------------
// Persistent per-layer GRU kernel. Weights pre-rounded tf32; next-step weight
// chunk prefetched across the grid barrier. 2-stage cp.async, static smem.
// Grid: 128 blocks (32 col x 4 rowgroups), 128 threads (4 warps).
// ---------------------------------------------------------------------------
#define SA_W (32 * GP)
#define SB_W (96 * GP)

__global__ __launch_bounds__(128) void gru_layer(const float* __restrict__ XI,     // [T,B,3H]
                                                 const uint32_t* __restrict__ WhhT,// [3H,H] tf32
                                                 const float* __restrict__ bhh,    // [3H]
                                                 float* __restrict__ hseq) {       // [T,B,H]
    __shared__ uint32_t sA[2 * SA_W];
    __shared__ uint32_t sB[2 * SB_W];

    int tid = threadIdx.x;
    int warp = tid >> 5, lane = tid & 31;
    int gid = lane >> 2, tig = lane & 3;
    int bx = blockIdx.x;
    int cb = bx & 31, rg = bx >> 5;
    int colBase = cb * 32;
    int rowBase = rg * 32;

    uint32_t sA_base = (uint32_t)__cvta_generic_to_shared(sA);
    uint32_t sB_base = (uint32_t)__cvta_generic_to_shared(sB);

    auto prefA = [&](const float* hp, int k0, int st) {
#pragma unroll
        for (int i = 0; i < 2; i++) {
            int f4 = tid + i * 128;
            int r = f4 >> 3, c4 = f4 & 7;
            cp16(sA_base + (st * SA_W + r * GP + c4 * 4) * 4,
                 &hp[(size_t)(rowBase + r) * HH + k0 + c4 * 4]);
        }
    };
    auto prefB = [&](int k0, int st) {
#pragma unroll
        for (int i = 0; i < 6; i++) {
            int f4 = tid + i * 128;
            int row96 = f4 >> 3, c4 = f4 & 7;
            int g = row96 >> 5, rr = row96 & 31;
            cp16(sB_base + (st * SB_W + row96 * GP + c4 * 4) * 4,
                 &WhhT[(size_t)(g * HH + colBase + rr) * HH + k0 + c4 * 4]);
        }
    };

    int col0 = colBase + warp * 8 + 2 * tig;
    float2 ebr = *reinterpret_cast<const float2*>(&bhh[col0]);
    float2 ebz = *reinterpret_cast<const float2*>(&bhh[HH + col0]);
    float2 ebn = *reinterpret_cast<const float2*>(&bhh[2 * HH + col0]);

    // initial weight chunk 0 -> stage 0 (consumed at t=1)
    prefB(0, 0);
    cp_commit();

    for (int t = 0; t < TT; t++) {
        const float* hprev = hseq + (size_t)(t - 1) * BB * HH;  // deref only when t>0
        const float* xi_t = XI + (size_t)t * BB * G3;
        float* hout = hseq + (size_t)t * BB * HH;

        float acc[2][3][4];
#pragma unroll
        for (int mt = 0; mt < 2; mt++)
#pragma unroll
            for (int g = 0; g < 3; g++)
#pragma unroll
                for (int k = 0; k < 4; k++) acc[mt][g][k] = 0.f;

        if (t > 0) {
            prefA(hprev, 0, 0);
            cp_commit();                       // pending: {Bprev0, A0}

            for (int c = 0; c < 32; c++) {
                if (c < 31) {                  // chunk c+1 (A+B)
                    int k0 = (c + 1) * 32;
                    int st = (c + 1) & 1;
                    prefA(hprev, k0, st);
                    prefB(k0, st);
                } else {
                    prefB(0, 0);               // next step's weight chunk 0
                }
                cp_commit();
                cp_wait1();                    // retire chunk c's data
                __syncthreads();

                const uint32_t* cA = sA + (c & 1) * SA_W;
                const uint32_t* cB = sB + (c & 1) * SB_W;
#pragma unroll
                for (int ks = 0; ks < 4; ks++) {
                    int kk = ks * 8;
                    uint32_t a[2][4];
#pragma unroll
                    for (int mt = 0; mt < 2; mt++) {
                        int r0 = mt * 16 + gid;
                        a[mt][0] = f2tf32(cA[r0 * GP + kk + tig]);
                        a[mt][1] = f2tf32(cA[(r0 + 8) * GP + kk + tig]);
                        a[mt][2] = f2tf32(cA[r0 * GP + kk + tig + 4]);
                        a[mt][3] = f2tf32(cA[(r0 + 8) * GP + kk + tig + 4]);
                    }
#pragma unroll
                    for (int g = 0; g < 3; g++) {
                        int nrow = g * 32 + warp * 8 + gid;
                        uint32_t b[2] = {cB[nrow * GP + kk + tig],
                                         cB[nrow * GP + kk + tig + 4]};
#pragma unroll
                        for (int mt = 0; mt < 2; mt++) mma_tf32(acc[mt][g], a[mt], b);
                    }
                }
                __syncthreads();               // stage fully read before reuse
            }
            // pending: {Bnext0}
        }

        // Gate fusion in registers
#pragma unroll
        for (int mt = 0; mt < 2; mt++) {
#pragma unroll
            for (int kp = 0; kp < 2; kp++) {
                int grow = rowBase + mt * 16 + gid + kp * 8;
                const float* xi = xi_t + (size_t)grow * G3 + col0;
                float2 xr = *reinterpret_cast<const float2*>(xi);
                float2 xz = *reinterpret_cast<const float2*>(xi + HH);
                float2 xn = *reinterpret_cast<const float2*>(xi + 2 * HH);
                float2 hp = {0.f, 0.f};
                if (t > 0)
                    hp = *reinterpret_cast<const float2*>(&hprev[(size_t)grow * HH + col0]);

                float rv0 = acc[mt][0][kp * 2], rv1 = acc[mt][0][kp * 2 + 1];
                float zv0 = acc[mt][1][kp * 2], zv1 = acc[mt][1][kp * 2 + 1];
                float nv0 = acc[mt][2][kp * 2], nv1 = acc[mt][2][kp * 2 + 1];

                float r0 = 1.f / (1.f + __expf(-(xr.x + rv0 + ebr.x)));
                float r1 = 1.f / (1.f + __expf(-(xr.y + rv1 + ebr.y)));
                float z0 = 1.f / (1.f + __expf(-(xz.x + zv0 + ebz.x)));
                float z1 = 1.f / (1.f + __expf(-(xz.y + zv1 + ebz.y)));
                float n0 = tanhf(xn.x + r0 * (nv0 + ebn.x));
                float n1 = tanhf(xn.y + r1 * (nv1 + ebn.y));
                float2 hv = {(1.f - z0) * n0 + z0 * hp.x,
                             (1.f - z1) * n1 + z1 * hp.y};
                *reinterpret_cast<float2*>(&hout[(size_t)grow * HH + col0]) = hv;
            }
        }

        if (t < TT - 1) rowgroup_sync(rg);
    }
    cp_wait0();   // drain the final speculative weight prefetch
}

// ---------------------------------------------------------------------------
// FC head
// ---------------------------------------------------------------------------
__global__ __launch_bounds__(256) void fc_kernel(const float* __restrict__ last,
                                                 const float* __restrict__ fcw,
                                                 const float* __restrict__ fcb,
                                                 float* __restrict__ out) {
    int warp = (blockIdx.x * blockDim.x + threadIdx.x) >> 5;
    int lane = threadIdx.x & 31;
    if (warp >= BB * PRED) return;
    int b = warp / PRED;
    int p = warp % PRED;
    float s = 0.f;
    const float* lrow = last + (size_t)b * HH;
    const float* wrow = fcw + (size_t)p * HH;
    for (int k = lane; k < HH; k += 32) s += lrow[k] * wrow[k];
#pragma unroll
    for (int off = 16; off; off >>= 1) s += __shfl_xor_sync(0xFFFFFFFFu, s, off);
    if (lane == 0) out[b * PRED + p] = s + fcb[p];
}

// ---------------------------------------------------------------------------
// Launcher: transpose(0), prep(1), [gemm,gru]x3 (2..7), fc(8)
// ---------------------------------------------------------------------------
extern "C" void kernel_launch(void* const* d_in, const int* in_sizes, int n_in,
                              void* d_out, int out_size) {
    const float* x = (const float*)d_in[0];
    const float* w_ih[3] = {(const float*)d_in[1], (const float*)d_in[5], (const float*)d_in[9]};
    const float* w_hh[3] = {(const float*)d_in[2], (const float*)d_in[6], (const float*)d_in[10]};
    const float* b_ih[3] = {(const float*)d_in[3], (const float*)d_in[7], (const float*)d_in[11]};
    const float* b_hh[3] = {(const float*)d_in[4], (const float*)d_in[8], (const float*)d_in[12]};
    const float* fcw = (const float*)d_in[13];
    const float* fcb = (const float*)d_in[14];
    float* out = (float*)d_out;

    float *XT, *XI, *HA, *HB;
    uint32_t *WIH, *WHH;
    cudaGetSymbolAddress((void**)&XT, g_XT);
    cudaGetSymbolAddress((void**)&XI, g_XI);
    cudaGetSymbolAddress((void**)&HA, g_HA);
    cudaGetSymbolAddress((void**)&HB, g_HB);
    cudaGetSymbolAddress((void**)&WIH, g_WIH);
    cudaGetSymbolAddress((void**)&WHH, g_WHH);
    const size_t WSTRIDE = (size_t)G3 * HH;

    {
        int total = TT * BB * INDIM;
        transpose_x<<<(total + 255) / 256, 256>>>(x, XT);
    }
    prep_weights<<<PREP_F4 / 256, 256>>>(w_ih[0], w_hh[0], w_ih[1], w_hh[1], w_ih[2], w_hh[2],
                                         WIH, WHH, WIH + WSTRIDE, WHH + WSTRIDE,
                                         WIH + 2 * WSTRIDE, WHH + 2 * WSTRIDE);

    const float* layin = XT;
    int Kin = INDIM;
    float* seqbuf[3] = {HA, HB, HA};

    for (int l = 0; l < 3; l++) {
        dim3 ggrid(G3 / 64, MROWS / 128);
        gemm_mma<<<ggrid, 256>>>(layin, WIH + (size_t)l * WSTRIDE, b_ih[l], XI, MROWS, G3, Kin);

        gru_layer<<<NCOLB * NROWB, 128>>>(XI, WHH + (size_t)l * WSTRIDE, b_hh[l], seqbuf[l]);

        layin = seqbuf[l];
        Kin = HH;
    }

    {
        const float* last = seqbuf[2] + (size_t)(TT - 1) * BB * HH;
        int warps = BB * PRED;
        int blocks = (warps * 32 + 255) / 256;
        fc_kernel<<<blocks, 256>>>(last, fcw, fcb, out);
    }
}

// round 7
// speedup vs baseline: 3.1017x; 1.1363x over previous
#include <cuda_runtime.h>
#include <math.h>
#include <stdint.h>

// Problem constants
#define BB   128
#define TT   512
#define INDIM 128
#define HH   1024
#define G3   (3*HH)
#define PRED 96
#define MROWS (TT*BB)

#define NCOLB 32          // H/32 col blocks
#define NROWB 4           // B/32 row groups

// ---------------------------------------------------------------------------
// Scratch
// ---------------------------------------------------------------------------
__device__ float g_XT[(size_t)TT * BB * INDIM];
__device__ float g_XI[(size_t)TT * BB * G3];
__device__ float g_HA[(size_t)TT * BB * HH];
__device__ float g_HB[(size_t)TT * BB * HH];
__device__ uint32_t g_WIH[3][(size_t)G3 * HH];   // tf32 std layout (layer 0 uses G3*INDIM)
__device__ uint2 g_WHHP[3][(size_t)32 * 4 * 3 * 128 * 32];  // fragment-permuted W_hh
__device__ uint4 g_HP[2][32768];                 // fragment-permuted h, ping-pong

__device__ unsigned g_cnt[NROWB];
__device__ unsigned g_gen[NROWB];

// ---------------------------------------------------------------------------
// PTX helpers
// ---------------------------------------------------------------------------
__device__ __forceinline__ void mma_tf32(float c[4], const uint32_t a[4], const uint32_t b[2]) {
    asm volatile(
        "mma.sync.aligned.m16n8k8.row.col.f32.tf32.tf32.f32 "
        "{%0,%1,%2,%3}, {%4,%5,%6,%7}, {%8,%9}, {%0,%1,%2,%3};\n"
        : "+f"(c[0]), "+f"(c[1]), "+f"(c[2]), "+f"(c[3])
        : "r"(a[0]), "r"(a[1]), "r"(a[2]), "r"(a[3]), "r"(b[0]), "r"(b[1]));
}
__device__ __forceinline__ uint32_t f2tf32(uint32_t x) {
    uint32_t y;
    asm volatile("cvt.rna.tf32.f32 %0, %1;" : "=r"(y) : "r"(x));
    return y;
}

// ---------------------------------------------------------------------------
// transpose x [B,T,IN] -> [T,B,IN]
// ---------------------------------------------------------------------------
__global__ __launch_bounds__(256) void transpose_x(const float* __restrict__ x,
                                                   float* __restrict__ xt) {
    int idx = blockIdx.x * blockDim.x + threadIdx.x;
    if (idx >= TT * BB * INDIM) return;
    int i = idx % INDIM;
    int r = idx / INDIM;
    int b = r % BB;
    int t = r / BB;
    xt[idx] = x[((size_t)b * TT + t) * INDIM + i];
}

// ---------------------------------------------------------------------------
// prep: (a) round w_ih to tf32 (standard layout); (b) build fragment-permuted
// tf32 W_hh for the recurrent kernel.
// ---------------------------------------------------------------------------
#define WIH_F4_0 (G3 * INDIM / 4)            // 98304
#define WIH_F4_1 (G3 * HH / 4)               // 786432
#define PREP_WIH (WIH_F4_0 + 2 * WIH_F4_1)   // 1671168
#define WHHP_L   (32 * 4 * 3 * 128 * 32)     // 1572864 uint2 per layer
#define PREP_TOTAL (PREP_WIH + 3 * WHHP_L)   // 6389760 = 24960*256

__global__ __launch_bounds__(256) void prep_weights(
    const float* __restrict__ wih0, const float* __restrict__ wih1,
    const float* __restrict__ wih2,
    const float* __restrict__ whh0, const float* __restrict__ whh1,
    const float* __restrict__ whh2) {
    long idx = (long)blockIdx.x * 256 + threadIdx.x;
    if (idx < PREP_WIH) {
        const float* src; uint32_t* dst; long off;
        if (idx < WIH_F4_0)                    { src = wih0; dst = g_WIH[0]; off = idx; }
        else if (idx < WIH_F4_0 + WIH_F4_1)    { src = wih1; dst = g_WIH[1]; off = idx - WIH_F4_0; }
        else                                   { src = wih2; dst = g_WIH[2]; off = idx - WIH_F4_0 - WIH_F4_1; }
        uint4 v = *reinterpret_cast<const uint4*>(src + off * 4);
        v.x = f2tf32(v.x); v.y = f2tf32(v.y); v.z = f2tf32(v.z); v.w = f2tf32(v.w);
        *reinterpret_cast<uint4*>(dst + off * 4) = v;
    } else {
        long r = idx - PREP_WIH;
        int l = (int)(r / WHHP_L);
        long r2 = r % WHHP_L;          // = ((((cb*4+w)*3+g)*128+kf)*32+lane)
        int cb   = (int)(r2 / 49152);
        int r3   = (int)(r2 % 49152);
        int w    = r3 / 12288;
        int r4   = r3 % 12288;
        int g    = r4 / 4096;
        int r5   = r4 % 4096;
        int kf   = r5 / 32;
        int lane = r5 % 32;
        int gid = lane >> 2, tig = lane & 3;
        const float* whh = (l == 0) ? whh0 : (l == 1) ? whh1 : whh2;
        int row = g * HH + cb * 32 + w * 8 + gid;
        int col = kf * 8 + tig;
        uint2 v;
        v.x = f2tf32(__float_as_uint(whh[(size_t)row * HH + col]));
        v.y = f2tf32(__float_as_uint(whh[(size_t)row * HH + col + 4]));
        g_WHHP[l][r2] = v;
    }
}

// ---------------------------------------------------------------------------
// tf32 mma GEMM: C[M,N] = A[M,K] @ Wt[N,K]^T + bias[N]   (unchanged from r6)
// ---------------------------------------------------------------------------
#define GP 36
__global__ __launch_bounds__(256) void gemm_mma(const float* __restrict__ A,
                                                const uint32_t* __restrict__ Wt,
                                                const float* __restrict__ bias,
                                                float* __restrict__ C,
                                                int M, int N, int K) {
    __shared__ uint32_t As[128 * GP];
    __shared__ uint32_t Bs[64 * GP];

    int tid = threadIdx.x;
    int warp = tid >> 5, lane = tid & 31;
    int gid = lane >> 2, tig = lane & 3;
    int wm = warp & 3, wn = warp >> 2;
    int rowBase = blockIdx.y * 128;
    int colBase = blockIdx.x * 64;

    int ra[4], ca[4], rb[2], cb2[2];
#pragma unroll
    for (int i = 0; i < 4; i++) { int f4 = tid + i * 256; ra[i] = f4 >> 3; ca[i] = f4 & 7; }
#pragma unroll
    for (int i = 0; i < 2; i++) { int f4 = tid + i * 256; rb[i] = f4 >> 3; cb2[i] = f4 & 7; }

    float acc[2][4][4];
#pragma unroll
    for (int mt = 0; mt < 2; mt++)
#pragma unroll
        for (int nt = 0; nt < 4; nt++)
#pragma unroll
            for (int k = 0; k < 4; k++) acc[mt][nt][k] = 0.f;

    uint4 pa[4], pb[2];
#pragma unroll
    for (int i = 0; i < 4; i++)
        pa[i] = *reinterpret_cast<const uint4*>(&A[(size_t)(rowBase + ra[i]) * K + ca[i] * 4]);
#pragma unroll
    for (int i = 0; i < 2; i++)
        pb[i] = *reinterpret_cast<const uint4*>(&Wt[(size_t)(colBase + rb[i]) * K + cb2[i] * 4]);
#pragma unroll
    for (int i = 0; i < 4; i++) {
        uint4 v = pa[i];
        v.x = f2tf32(v.x); v.y = f2tf32(v.y); v.z = f2tf32(v.z); v.w = f2tf32(v.w);
        *reinterpret_cast<uint4*>(&As[ra[i] * GP + ca[i] * 4]) = v;
    }
#pragma unroll
    for (int i = 0; i < 2; i++)
        *reinterpret_cast<uint4*>(&Bs[rb[i] * GP + cb2[i] * 4]) = pb[i];
    __syncthreads();

    for (int k0 = 0; k0 < K; k0 += 32) {
        bool has_next = (k0 + 32 < K);
        if (has_next) {
#pragma unroll
            for (int i = 0; i < 4; i++)
                pa[i] = *reinterpret_cast<const uint4*>(&A[(size_t)(rowBase + ra[i]) * K + k0 + 32 + ca[i] * 4]);
#pragma unroll
            for (int i = 0; i < 2; i++)
                pb[i] = *reinterpret_cast<const uint4*>(&Wt[(size_t)(colBase + rb[i]) * K + k0 + 32 + cb2[i] * 4]);
        }
#pragma unroll
        for (int ks = 0; ks < 4; ks++) {
            int kk = ks * 8;
            uint32_t a[2][4];
#pragma unroll
            for (int mt = 0; mt < 2; mt++) {
                int r0 = wm * 32 + mt * 16 + gid;
                a[mt][0] = As[r0 * GP + kk + tig];
                a[mt][1] = As[(r0 + 8) * GP + kk + tig];
                a[mt][2] = As[r0 * GP + kk + tig + 4];
                a[mt][3] = As[(r0 + 8) * GP + kk + tig + 4];
            }
#pragma unroll
            for (int nt = 0; nt < 4; nt++) {
                int n0 = wn * 32 + nt * 8 + gid;
                uint32_t b[2] = {Bs[n0 * GP + kk + tig], Bs[n0 * GP + kk + tig + 4]};
#pragma unroll
                for (int mt = 0; mt < 2; mt++) mma_tf32(acc[mt][nt], a[mt], b);
            }
        }
        __syncthreads();
        if (has_next) {
#pragma unroll
            for (int i = 0; i < 4; i++) {
                uint4 v = pa[i];
                v.x = f2tf32(v.x); v.y = f2tf32(v.y); v.z = f2tf32(v.z); v.w = f2tf32(v.w);
                *reinterpret_cast<uint4*>(&As[ra[i] * GP + ca[i] * 4]) = v;
            }
#pragma unroll
            for (int i = 0; i < 2; i++)
                *reinterpret_cast<uint4*>(&Bs[rb[i] * GP + cb2[i] * 4]) = pb[i];
            __syncthreads();
        }
    }

#pragma unroll
    for (int mt = 0; mt < 2; mt++) {
        int row = rowBase + wm * 32 + mt * 16 + gid;
#pragma unroll
        for (int nt = 0; nt < 4; nt++) {
            int col = colBase + wn * 32 + nt * 8 + 2 * tig;
            float2 bi = *reinterpret_cast<const float2*>(&bias[col]);
            float2 v0 = {acc[mt][nt][0] + bi.x, acc[mt][nt][1] + bi.y};
            float2 v1 = {acc[mt][nt][2] + bi.x, acc[mt][nt][3] + bi.y};
            *reinterpret_cast<float2*>(&C[(size_t)row * N + col]) = v0;
            *reinterpret_cast<float2*>(&C[(size_t)(row + 8) * N + col]) = v1;
        }
    }
}

// ---------------------------------------------------------------------------
// Row-group grid barrier
// ---------------------------------------------------------------------------
__device__ __forceinline__ void rowgroup_sync(int rg) {
    __syncthreads();
    if (threadIdx.x == 0) {
        __threadfence();
        volatile unsigned* genp = &g_gen[rg];
        unsigned my = *genp;
        unsigned prev = atomicAdd(&g_cnt[rg], 1u);
        if (prev == NCOLB - 1) {
            atomicExch(&g_cnt[rg], 0u);
            __threadfence();
            *genp = my + 1;
        } else {
            while (*genp == my) { __nanosleep(32); }
        }
    }
    __syncthreads();
}

// ---------------------------------------------------------------------------
// Persistent per-layer GRU kernel, register-only pipeline.
// Operands arrive fragment-permuted: B (weights) via prep, A (h) written by
// the previous step's epilogue into hP (ping-pong by t parity).
// No shared memory, no syncs in the mainloop.
// Grid: 128 blocks (32 col x 4 rowgroups), 128 threads (4 warps).
// ---------------------------------------------------------------------------
__global__ __launch_bounds__(128, 1) void gru_layer(const float* __restrict__ XI,   // [T,B,3H]
                                                    const uint2* __restrict__ wP,   // permuted Whh
                                                    const float* __restrict__ bhh,  // [3H]
                                                    float* __restrict__ hseq,       // [T,B,H]
                                                    uint4* __restrict__ hP) {       // [2][32768]
    int tid = threadIdx.x;
    int warp = tid >> 5, lane = tid & 31;
    int gid = lane >> 2, tig = lane & 3;
    int bx = blockIdx.x;
    int cb = bx & 31, rg = bx >> 5;
    int colBase = cb * 32;
    int rowBase = rg * 32;

    // thread-base pointer into permuted weights: offset (g,kf) = (g*128+kf)*32
    const uint2* wPt = wP + ((size_t)(cb * 4 + warp) * 3 * 128) * 32 + lane;

    int col0 = colBase + warp * 8 + 2 * tig;
    float2 ebr = *reinterpret_cast<const float2*>(&bhh[col0]);
    float2 ebz = *reinterpret_cast<const float2*>(&bhh[HH + col0]);
    float2 ebn = *reinterpret_cast<const float2*>(&bhh[2 * HH + col0]);

    int kfg = cb * 4 + warp;                       // this warp's k8-column in hP terms

    for (int t = 0; t < TT; t++) {
        const float* hprev = hseq + (size_t)(t - 1) * BB * HH;   // deref only for t>0
        const float* xi_t = XI + (size_t)t * BB * G3;
        float* hout = hseq + (size_t)t * BB * HH;

        float acc[2][3][4];
#pragma unroll
        for (int mt = 0; mt < 2; mt++)
#pragma unroll
            for (int g = 0; g < 3; g++)
#pragma unroll
                for (int k = 0; k < 4; k++) acc[mt][g][k] = 0.f;

        if (t > 0) {
            // A fragments from previous step's permuted buffer (bypass L1: lines
            // are rewritten by other SMs every other step)
            const uint4* hPr = hP + ((size_t)((t - 1) & 1)) * 32768
                                 + (size_t)rg * 128 * 2 * 32 + lane;
            // offset (kf,mt) = (kf*2+mt)*32

            auto pref = [&](int c, uint4 (&A)[8], uint2 (&B)[12]) {
#pragma unroll
                for (int ks = 0; ks < 4; ks++)
#pragma unroll
                    for (int mt = 0; mt < 2; mt++)
                        A[ks * 2 + mt] = __ldcg(hPr + ((c * 4 + ks) * 2 + mt) * 32);
#pragma unroll
                for (int g = 0; g < 3; g++)
#pragma unroll
                    for (int ks = 0; ks < 4; ks++)
                        B[g * 4 + ks] = __ldg(wPt + (g * 128 + c * 4 + ks) * 32);
            };
            auto comp = [&](const uint4 (&A)[8], const uint2 (&B)[12]) {
#pragma unroll
                for (int ks = 0; ks < 4; ks++) {
                    uint32_t a0[4] = {A[ks * 2].x, A[ks * 2].y, A[ks * 2].z, A[ks * 2].w};
                    uint32_t a1[4] = {A[ks * 2 + 1].x, A[ks * 2 + 1].y,
                                      A[ks * 2 + 1].z, A[ks * 2 + 1].w};
#pragma unroll
                    for (int g = 0; g < 3; g++) {
                        uint32_t b[2] = {B[g * 4 + ks].x, B[g * 4 + ks].y};
                        mma_tf32(acc[0][g], a0, b);
                        mma_tf32(acc[1][g], a1, b);
                    }
                }
            };

            uint4 A0[8], A1[8];
            uint2 B0[12], B1[12];
            pref(0, A0, B0);
            pref(1, A1, B1);
#pragma unroll 1
            for (int cc = 0; cc < 16; cc++) {
                comp(A0, B0);
                if (cc < 15) pref(2 * cc + 2, A0, B0);
                comp(A1, B1);
                if (cc < 15) pref(2 * cc + 3, A1, B1);
            }
        }

        // Epilogue: gate fusion in registers; write standard h and permuted hP
        uint32_t* hPw = reinterpret_cast<uint32_t*>(hP + ((size_t)(t & 1)) * 32768);
#pragma unroll
        for (int mt = 0; mt < 2; mt++) {
            int base4 = ((rg * 128 + kfg) * 2 + mt) * 32;
#pragma unroll
            for (int kp = 0; kp < 2; kp++) {
                int grow = rowBase + mt * 16 + gid + kp * 8;
                const float* xi = xi_t + (size_t)grow * G3 + col0;
                float2 xr = *reinterpret_cast<const float2*>(xi);
                float2 xz = *reinterpret_cast<const float2*>(xi + HH);
                float2 xn = *reinterpret_cast<const float2*>(xi + 2 * HH);
                float2 hp = {0.f, 0.f};
                if (t > 0)
                    hp = *reinterpret_cast<const float2*>(&hprev[(size_t)grow * HH + col0]);

                float rv0 = acc[mt][0][kp * 2], rv1 = acc[mt][0][kp * 2 + 1];
                float zv0 = acc[mt][1][kp * 2], zv1 = acc[mt][1][kp * 2 + 1];
                float nv0 = acc[mt][2][kp * 2], nv1 = acc[mt][2][kp * 2 + 1];

                float r0 = 1.f / (1.f + __expf(-(xr.x + rv0 + ebr.x)));
                float r1 = 1.f / (1.f + __expf(-(xr.y + rv1 + ebr.y)));
                float z0 = 1.f / (1.f + __expf(-(xz.x + zv0 + ebz.x)));
                float z1 = 1.f / (1.f + __expf(-(xz.y + zv1 + ebz.y)));
                float n0 = tanhf(xn.x + r0 * (nv0 + ebn.x));
                float n1 = tanhf(xn.y + r1 * (nv1 + ebn.y));
                float h0 = (1.f - z0) * n0 + z0 * hp.x;
                float h1 = (1.f - z1) * n1 + z1 * hp.y;

                *reinterpret_cast<float2*>(&hout[(size_t)grow * HH + col0]) =
                    make_float2(h0, h1);

                // permuted tf32 copy for next step's A operand
#pragma unroll
                for (int j = 0; j < 2; j++) {
                    int cc2 = 2 * tig + j;
                    int lanep = gid * 4 + (cc2 & 3);
                    int w = (cc2 >> 2) * 2 + kp;
                    uint32_t hv = __float_as_uint(j == 0 ? h0 : h1);
                    hPw[(base4 + lanep) * 4 + w] = f2tf32(hv);
                }
            }
        }

        if (t < TT - 1) rowgroup_sync(rg);
    }
}

// ---------------------------------------------------------------------------
// FC head
// ---------------------------------------------------------------------------
__global__ __launch_bounds__(256) void fc_kernel(const float* __restrict__ last,
                                                 const float* __restrict__ fcw,
                                                 const float* __restrict__ fcb,
                                                 float* __restrict__ out) {
    int warp = (blockIdx.x * blockDim.x + threadIdx.x) >> 5;
    int lane = threadIdx.x & 31;
    if (warp >= BB * PRED) return;
    int b = warp / PRED;
    int p = warp % PRED;
    float s = 0.f;
    const float* lrow = last + (size_t)b * HH;
    const float* wrow = fcw + (size_t)p * HH;
    for (int k = lane; k < HH; k += 32) s += lrow[k] * wrow[k];
#pragma unroll
    for (int off = 16; off; off >>= 1) s += __shfl_xor_sync(0xFFFFFFFFu, s, off);
    if (lane == 0) out[b * PRED + p] = s + fcb[p];
}

// ---------------------------------------------------------------------------
// Launcher: transpose(0), prep(1), gemm0(2), gru0(3), gemm1(4), gru1(5), ...
// ---------------------------------------------------------------------------
extern "C" void kernel_launch(void* const* d_in, const int* in_sizes, int n_in,
                              void* d_out, int out_size) {
    const float* x = (const float*)d_in[0];
    const float* w_ih[3] = {(const float*)d_in[1], (const float*)d_in[5], (const float*)d_in[9]};
    const float* w_hh[3] = {(const float*)d_in[2], (const float*)d_in[6], (const float*)d_in[10]};
    const float* b_ih[3] = {(const float*)d_in[3], (const float*)d_in[7], (const float*)d_in[11]};
    const float* b_hh[3] = {(const float*)d_in[4], (const float*)d_in[8], (const float*)d_in[12]};
    const float* fcw = (const float*)d_in[13];
    const float* fcb = (const float*)d_in[14];
    float* out = (float*)d_out;

    float *XT, *XI, *HA, *HB;
    uint32_t* WIH;
    uint2* WHHP;
    uint4* HP;
    cudaGetSymbolAddress((void**)&XT, g_XT);
    cudaGetSymbolAddress((void**)&XI, g_XI);
    cudaGetSymbolAddress((void**)&HA, g_HA);
    cudaGetSymbolAddress((void**)&HB, g_HB);
    cudaGetSymbolAddress((void**)&WIH, g_WIH);
    cudaGetSymbolAddress((void**)&WHHP, g_WHHP);
    cudaGetSymbolAddress((void**)&HP, g_HP);
    const size_t WSTRIDE = (size_t)G3 * HH;

    {
        int total = TT * BB * INDIM;
        transpose_x<<<(total + 255) / 256, 256>>>(x, XT);
    }
    prep_weights<<<PREP_TOTAL / 256, 256>>>(w_ih[0], w_ih[1], w_ih[2],
                                            w_hh[0], w_hh[1], w_hh[2]);

    const float* layin = XT;
    int Kin = INDIM;
    float* seqbuf[3] = {HA, HB, HA};

    for (int l = 0; l < 3; l++) {
        dim3 ggrid(G3 / 64, MROWS / 128);
        gemm_mma<<<ggrid, 256>>>(layin, WIH + (size_t)l * WSTRIDE, b_ih[l], XI, MROWS, G3, Kin);

        gru_layer<<<NCOLB * NROWB, 128>>>(XI, WHHP + (size_t)l * WHHP_L, b_hh[l],
                                          seqbuf[l], HP);

        layin = seqbuf[l];
        Kin = HH;
    }

    {
        const float* last = seqbuf[2] + (size_t)(TT - 1) * BB * HH;
        int warps = BB * PRED;
        int blocks = (warps * 32 + 255) / 256;
        fc_kernel<<<blocks, 256>>>(last, fcw, fcb, out);
    }
}

// round 10
// speedup vs baseline: 3.6579x; 1.1793x over previous
#include <cuda_runtime.h>
#include <math.h>
#include <stdint.h>

// Problem constants
#define BB   128
#define TT   512
#define INDIM 128
#define HH   1024
#define G3   (3*HH)
#define PRED 96
#define MROWS (TT*BB)

#define NCOLB 32          // H/32 col blocks
#define NROWB 4           // B/32 row groups

// ---------------------------------------------------------------------------
// Scratch
// ---------------------------------------------------------------------------
__device__ float g_XT[(size_t)TT * BB * INDIM];
__device__ float g_XI[(size_t)TT * BB * G3];
__device__ float g_HA[(size_t)TT * BB * HH];
__device__ float g_HB[(size_t)TT * BB * HH];
__device__ uint32_t g_WIH[3][(size_t)G3 * HH];   // tf32 std layout (layer 0 uses G3*INDIM)
__device__ uint2 g_WHHP[3][(size_t)32 * 4 * 3 * 128 * 32];  // fragment-permuted W_hh
__device__ uint4 g_HP[2][32768];                 // fragment-permuted h, ping-pong

__device__ unsigned g_cnt[NROWB];
__device__ unsigned g_gen[NROWB];

// ---------------------------------------------------------------------------
// PTX helpers
// ---------------------------------------------------------------------------
__device__ __forceinline__ void mma_tf32(float c[4], const uint32_t a[4], const uint32_t b[2]) {
    asm volatile(
        "mma.sync.aligned.m16n8k8.row.col.f32.tf32.tf32.f32 "
        "{%0,%1,%2,%3}, {%4,%5,%6,%7}, {%8,%9}, {%0,%1,%2,%3};\n"
        : "+f"(c[0]), "+f"(c[1]), "+f"(c[2]), "+f"(c[3])
        : "r"(a[0]), "r"(a[1]), "r"(a[2]), "r"(a[3]), "r"(b[0]), "r"(b[1]));
}
__device__ __forceinline__ uint32_t f2tf32(uint32_t x) {
    uint32_t y;
    asm volatile("cvt.rna.tf32.f32 %0, %1;" : "=r"(y) : "r"(x));
    return y;
}

// ---------------------------------------------------------------------------
// transpose x [B,T,IN] -> [T,B,IN]
// ---------------------------------------------------------------------------
__global__ __launch_bounds__(256) void transpose_x(const float* __restrict__ x,
                                                   float* __restrict__ xt) {
    int idx = blockIdx.x * blockDim.x + threadIdx.x;
    if (idx >= TT * BB * INDIM) return;
    int i = idx % INDIM;
    int r = idx / INDIM;
    int b = r % BB;
    int t = r / BB;
    xt[idx] = x[((size_t)b * TT + t) * INDIM + i];
}

// ---------------------------------------------------------------------------
// prep: (a) round w_ih to tf32; (b) fragment-permuted tf32 W_hh
// ---------------------------------------------------------------------------
#define WIH_F4_0 (G3 * INDIM / 4)            // 98304
#define WIH_F4_1 (G3 * HH / 4)               // 786432
#define PREP_WIH (WIH_F4_0 + 2 * WIH_F4_1)   // 1671168
#define WHHP_L   (32 * 4 * 3 * 128 * 32)     // 1572864 uint2 per layer
#define PREP_TOTAL (PREP_WIH + 3 * WHHP_L)   // 6389760 = 24960*256

__global__ __launch_bounds__(256) void prep_weights(
    const float* __restrict__ wih0, const float* __restrict__ wih1,
    const float* __restrict__ wih2,
    const float* __restrict__ whh0, const float* __restrict__ whh1,
    const float* __restrict__ whh2) {
    long idx = (long)blockIdx.x * 256 + threadIdx.x;
    if (idx < PREP_WIH) {
        const float* src; uint32_t* dst; long off;
        if (idx < WIH_F4_0)                    { src = wih0; dst = g_WIH[0]; off = idx; }
        else if (idx < WIH_F4_0 + WIH_F4_1)    { src = wih1; dst = g_WIH[1]; off = idx - WIH_F4_0; }
        else                                   { src = wih2; dst = g_WIH[2]; off = idx - WIH_F4_0 - WIH_F4_1; }
        uint4 v = *reinterpret_cast<const uint4*>(src + off * 4);
        v.x = f2tf32(v.x); v.y = f2tf32(v.y); v.z = f2tf32(v.z); v.w = f2tf32(v.w);
        *reinterpret_cast<uint4*>(dst + off * 4) = v;
    } else {
        long r = idx - PREP_WIH;
        int l = (int)(r / WHHP_L);
        long r2 = r % WHHP_L;          // = ((((cb*4+w)*3+g)*128+kf)*32+lane)
        int cb   = (int)(r2 / 49152);
        int r3   = (int)(r2 % 49152);
        int w    = r3 / 12288;
        int r4   = r3 % 12288;
        int g    = r4 / 4096;
        int r5   = r4 % 4096;
        int kf   = r5 / 32;
        int lane = r5 % 32;
        int gid = lane >> 2, tig = lane & 3;
        const float* whh = (l == 0) ? whh0 : (l == 1) ? whh1 : whh2;
        int row = g * HH + cb * 32 + w * 8 + gid;
        int col = kf * 8 + tig;
        uint2 v;
        v.x = f2tf32(__float_as_uint(whh[(size_t)row * HH + col]));
        v.y = f2tf32(__float_as_uint(whh[(size_t)row * HH + col + 4]));
        g_WHHP[l][r2] = v;
    }
}

// ---------------------------------------------------------------------------
// tf32 mma GEMM: C[M,N] = A[M,K] @ Wt[N,K]^T + bias[N]   (unchanged)
// ---------------------------------------------------------------------------
#define GP 36
__global__ __launch_bounds__(256) void gemm_mma(const float* __restrict__ A,
                                                const uint32_t* __restrict__ Wt,
                                                const float* __restrict__ bias,
                                                float* __restrict__ C,
                                                int M, int N, int K) {
    __shared__ uint32_t As[128 * GP];
    __shared__ uint32_t Bs[64 * GP];

    int tid = threadIdx.x;
    int warp = tid >> 5, lane = tid & 31;
    int gid = lane >> 2, tig = lane & 3;
    int wm = warp & 3, wn = warp >> 2;
    int rowBase = blockIdx.y * 128;
    int colBase = blockIdx.x * 64;

    int ra[4], ca[4], rb[2], cb2[2];
#pragma unroll
    for (int i = 0; i < 4; i++) { int f4 = tid + i * 256; ra[i] = f4 >> 3; ca[i] = f4 & 7; }
#pragma unroll
    for (int i = 0; i < 2; i++) { int f4 = tid + i * 256; rb[i] = f4 >> 3; cb2[i] = f4 & 7; }

    float acc[2][4][4];
#pragma unroll
    for (int mt = 0; mt < 2; mt++)
#pragma unroll
        for (int nt = 0; nt < 4; nt++)
#pragma unroll
            for (int k = 0; k < 4; k++) acc[mt][nt][k] = 0.f;

    uint4 pa[4], pb[2];
#pragma unroll
    for (int i = 0; i < 4; i++)
        pa[i] = *reinterpret_cast<const uint4*>(&A[(size_t)(rowBase + ra[i]) * K + ca[i] * 4]);
#pragma unroll
    for (int i = 0; i < 2; i++)
        pb[i] = *reinterpret_cast<const uint4*>(&Wt[(size_t)(colBase + rb[i]) * K + cb2[i] * 4]);
#pragma unroll
    for (int i = 0; i < 4; i++) {
        uint4 v = pa[i];
        v.x = f2tf32(v.x); v.y = f2tf32(v.y); v.z = f2tf32(v.z); v.w = f2tf32(v.w);
        *reinterpret_cast<uint4*>(&As[ra[i] * GP + ca[i] * 4]) = v;
    }
#pragma unroll
    for (int i = 0; i < 2; i++)
        *reinterpret_cast<uint4*>(&Bs[rb[i] * GP + cb2[i] * 4]) = pb[i];
    __syncthreads();

    for (int k0 = 0; k0 < K; k0 += 32) {
        bool has_next = (k0 + 32 < K);
        if (has_next) {
#pragma unroll
            for (int i = 0; i < 4; i++)
                pa[i] = *reinterpret_cast<const uint4*>(&A[(size_t)(rowBase + ra[i]) * K + k0 + 32 + ca[i] * 4]);
#pragma unroll
            for (int i = 0; i < 2; i++)
                pb[i] = *reinterpret_cast<const uint4*>(&Wt[(size_t)(colBase + rb[i]) * K + k0 + 32 + cb2[i] * 4]);
        }
#pragma unroll
        for (int ks = 0; ks < 4; ks++) {
            int kk = ks * 8;
            uint32_t a[2][4];
#pragma unroll
            for (int mt = 0; mt < 2; mt++) {
                int r0 = wm * 32 + mt * 16 + gid;
                a[mt][0] = As[r0 * GP + kk + tig];
                a[mt][1] = As[(r0 + 8) * GP + kk + tig];
                a[mt][2] = As[r0 * GP + kk + tig + 4];
                a[mt][3] = As[(r0 + 8) * GP + kk + tig + 4];
            }
#pragma unroll
            for (int nt = 0; nt < 4; nt++) {
                int n0 = wn * 32 + nt * 8 + gid;
                uint32_t b[2] = {Bs[n0 * GP + kk + tig], Bs[n0 * GP + kk + tig + 4]};
#pragma unroll
                for (int mt = 0; mt < 2; mt++) mma_tf32(acc[mt][nt], a[mt], b);
            }
        }
        __syncthreads();
        if (has_next) {
#pragma unroll
            for (int i = 0; i < 4; i++) {
                uint4 v = pa[i];
                v.x = f2tf32(v.x); v.y = f2tf32(v.y); v.z = f2tf32(v.z); v.w = f2tf32(v.w);
                *reinterpret_cast<uint4*>(&As[ra[i] * GP + ca[i] * 4]) = v;
            }
#pragma unroll
            for (int i = 0; i < 2; i++)
                *reinterpret_cast<uint4*>(&Bs[rb[i] * GP + cb2[i] * 4]) = pb[i];
            __syncthreads();
        }
    }

#pragma unroll
    for (int mt = 0; mt < 2; mt++) {
        int row = rowBase + wm * 32 + mt * 16 + gid;
#pragma unroll
        for (int nt = 0; nt < 4; nt++) {
            int col = colBase + wn * 32 + nt * 8 + 2 * tig;
            float2 bi = *reinterpret_cast<const float2*>(&bias[col]);
            float2 v0 = {acc[mt][nt][0] + bi.x, acc[mt][nt][1] + bi.y};
            float2 v1 = {acc[mt][nt][2] + bi.x, acc[mt][nt][3] + bi.y};
            *reinterpret_cast<float2*>(&C[(size_t)row * N + col]) = v0;
            *reinterpret_cast<float2*>(&C[(size_t)(row + 8) * N + col]) = v1;
        }
    }
}

// ---------------------------------------------------------------------------
// Row-group grid barrier (proven in rounds 2/5/6/7)
// ---------------------------------------------------------------------------
__device__ __forceinline__ void rowgroup_sync(int rg) {
    __syncthreads();
    if (threadIdx.x == 0) {
        __threadfence();
        volatile unsigned* genp = &g_gen[rg];
        unsigned my = *genp;
        unsigned prev = atomicAdd(&g_cnt[rg], 1u);
        if (prev == NCOLB - 1) {
            atomicExch(&g_cnt[rg], 0u);
            __threadfence();
            *genp = my + 1;
        } else {
            while (*genp == my) { __nanosleep(32); }
        }
    }
    __syncthreads();
}

// ---------------------------------------------------------------------------
// Persistent per-layer GRU kernel, register-only pipeline, M-SPLIT:
// 256 threads / 8 warps. Warp w: ww=w&3 owns H-cols [ww*8,ww*8+8) (all gates),
// wm=w>>2 owns m16 half wm of the 32 batch rows. Each warp runs the full
// 32-chunk K loop with half the per-chunk work; no smem, no reduction.
// Grid: 128 blocks (32 col x 4 rowgroups).
// ---------------------------------------------------------------------------
__global__ __launch_bounds__(256, 1) void gru_layer(const float* __restrict__ XI,   // [T,B,3H]
                                                    const uint2* __restrict__ wP,   // permuted Whh
                                                    const float* __restrict__ bhh,  // [3H]
                                                    float* __restrict__ hseq,       // [T,B,H]
                                                    uint4* __restrict__ hP) {       // [2][32768]
    int tid = threadIdx.x;
    int warp = tid >> 5, lane = tid & 31;
    int gid = lane >> 2, tig = lane & 3;
    int ww = warp & 3;        // n8-column owner
    int wm = warp >> 2;       // m16-half owner
    int bx = blockIdx.x;
    int cb = bx & 31, rg = bx >> 5;
    int colBase = cb * 32;
    int rowBase = rg * 32;

    // thread-base pointer into permuted weights: offset (g,kf) = (g*128+kf)*32
    const uint2* wPt = wP + ((size_t)(cb * 4 + ww) * 3 * 128) * 32 + lane;

    int col0 = colBase + ww * 8 + 2 * tig;
    float2 ebr = *reinterpret_cast<const float2*>(&bhh[col0]);
    float2 ebz = *reinterpret_cast<const float2*>(&bhh[HH + col0]);
    float2 ebn = *reinterpret_cast<const float2*>(&bhh[2 * HH + col0]);

    int kfg = cb * 4 + ww;                 // this warp's k8-column in hP terms

    for (int t = 0; t < TT; t++) {
        const float* hprev = hseq + (size_t)(t - 1) * BB * HH;   // deref only for t>0
        const float* xi_t = XI + (size_t)t * BB * G3;
        float* hout = hseq + (size_t)t * BB * HH;

        float acc[3][4];
#pragma unroll
        for (int g = 0; g < 3; g++)
#pragma unroll
            for (int k = 0; k < 4; k++) acc[g][k] = 0.f;

        if (t > 0) {
            const uint4* hPr = hP + ((size_t)((t - 1) & 1)) * 32768
                                 + (size_t)rg * 128 * 2 * 32 + lane;

            auto pref = [&](int c, uint4 (&A)[4], uint2 (&B)[12]) {
#pragma unroll
                for (int ks = 0; ks < 4; ks++)
                    A[ks] = __ldcg(hPr + ((c * 4 + ks) * 2 + wm) * 32);
#pragma unroll
                for (int g = 0; g < 3; g++)
#pragma unroll
                    for (int ks = 0; ks < 4; ks++)
                        B[g * 4 + ks] = __ldg(wPt + (g * 128 + c * 4 + ks) * 32);
            };
            auto comp = [&](const uint4 (&A)[4], const uint2 (&B)[12]) {
#pragma unroll
                for (int ks = 0; ks < 4; ks++) {
                    uint32_t a[4] = {A[ks].x, A[ks].y, A[ks].z, A[ks].w};
#pragma unroll
                    for (int g = 0; g < 3; g++) {
                        uint32_t b[2] = {B[g * 4 + ks].x, B[g * 4 + ks].y};
                        mma_tf32(acc[g], a, b);
                    }
                }
            };

            uint4 A0[4], A1[4];
            uint2 B0[12], B1[12];
            pref(0, A0, B0);
            pref(1, A1, B1);
#pragma unroll 1
            for (int cc = 0; cc < 16; cc++) {
                comp(A0, B0);
                if (cc < 15) pref(2 * cc + 2, A0, B0);
                comp(A1, B1);
                if (cc < 15) pref(2 * cc + 3, A1, B1);
            }
        }

        // Epilogue: this warp's m16 half only; gate fusion in registers
        {
            uint32_t* hPw = reinterpret_cast<uint32_t*>(hP + ((size_t)(t & 1)) * 32768);
            int base4 = ((rg * 128 + kfg) * 2 + wm) * 32;
#pragma unroll
            for (int kp = 0; kp < 2; kp++) {
                int grow = rowBase + wm * 16 + gid + kp * 8;
                const float* xi = xi_t + (size_t)grow * G3 + col0;
                float2 xr = *reinterpret_cast<const float2*>(xi);
                float2 xz = *reinterpret_cast<const float2*>(xi + HH);
                float2 xn = *reinterpret_cast<const float2*>(xi + 2 * HH);
                float2 hp = {0.f, 0.f};
                if (t > 0)
                    hp = *reinterpret_cast<const float2*>(&hprev[(size_t)grow * HH + col0]);

                float rv0 = acc[0][kp * 2], rv1 = acc[0][kp * 2 + 1];
                float zv0 = acc[1][kp * 2], zv1 = acc[1][kp * 2 + 1];
                float nv0 = acc[2][kp * 2], nv1 = acc[2][kp * 2 + 1];

                float r0 = 1.f / (1.f + __expf(-(xr.x + rv0 + ebr.x)));
                float r1 = 1.f / (1.f + __expf(-(xr.y + rv1 + ebr.y)));
                float z0 = 1.f / (1.f + __expf(-(xz.x + zv0 + ebz.x)));
                float z1 = 1.f / (1.f + __expf(-(xz.y + zv1 + ebz.y)));
                float n0 = tanhf(xn.x + r0 * (nv0 + ebn.x));
                float n1 = tanhf(xn.y + r1 * (nv1 + ebn.y));
                float h0 = (1.f - z0) * n0 + z0 * hp.x;
                float h1 = (1.f - z1) * n1 + z1 * hp.y;

                *reinterpret_cast<float2*>(&hout[(size_t)grow * HH + col0]) =
                    make_float2(h0, h1);

#pragma unroll
                for (int j = 0; j < 2; j++) {
                    int cc2 = 2 * tig + j;
                    int lanep = gid * 4 + (cc2 & 3);
                    int w = (cc2 >> 2) * 2 + kp;
                    uint32_t hv = __float_as_uint(j == 0 ? h0 : h1);
                    hPw[(base4 + lanep) * 4 + w] = f2tf32(hv);
                }
            }
        }

        if (t < TT - 1) rowgroup_sync(rg);
    }
}

// ---------------------------------------------------------------------------
// FC head
// ---------------------------------------------------------------------------
__global__ __launch_bounds__(256) void fc_kernel(const float* __restrict__ last,
                                                 const float* __restrict__ fcw,
                                                 const float* __restrict__ fcb,
                                                 float* __restrict__ out) {
    int warp = (blockIdx.x * blockDim.x + threadIdx.x) >> 5;
    int lane = threadIdx.x & 31;
    if (warp >= BB * PRED) return;
    int b = warp / PRED;
    int p = warp % PRED;
    float s = 0.f;
    const float* lrow = last + (size_t)b * HH;
    const float* wrow = fcw + (size_t)p * HH;
    for (int k = lane; k < HH; k += 32) s += lrow[k] * wrow[k];
#pragma unroll
    for (int off = 16; off; off >>= 1) s += __shfl_xor_sync(0xFFFFFFFFu, s, off);
    if (lane == 0) out[b * PRED + p] = s + fcb[p];
}

// ---------------------------------------------------------------------------
// Launcher
// ---------------------------------------------------------------------------
extern "C" void kernel_launch(void* const* d_in, const int* in_sizes, int n_in,
                              void* d_out, int out_size) {
    const float* x = (const float*)d_in[0];
    const float* w_ih[3] = {(const float*)d_in[1], (const float*)d_in[5], (const float*)d_in[9]};
    const float* w_hh[3] = {(const float*)d_in[2], (const float*)d_in[6], (const float*)d_in[10]};
    const float* b_ih[3] = {(const float*)d_in[3], (const float*)d_in[7], (const float*)d_in[11]};
    const float* b_hh[3] = {(const float*)d_in[4], (const float*)d_in[8], (const float*)d_in[12]};
    const float* fcw = (const float*)d_in[13];
    const float* fcb = (const float*)d_in[14];
    float* out = (float*)d_out;

    float *XT, *XI, *HA, *HB;
    uint32_t* WIH;
    uint2* WHHP;
    uint4* HP;
    cudaGetSymbolAddress((void**)&XT, g_XT);
    cudaGetSymbolAddress((void**)&XI, g_XI);
    cudaGetSymbolAddress((void**)&HA, g_HA);
    cudaGetSymbolAddress((void**)&HB, g_HB);
    cudaGetSymbolAddress((void**)&WIH, g_WIH);
    cudaGetSymbolAddress((void**)&WHHP, g_WHHP);
    cudaGetSymbolAddress((void**)&HP, g_HP);
    const size_t WSTRIDE = (size_t)G3 * HH;

    {
        int total = TT * BB * INDIM;
        transpose_x<<<(total + 255) / 256, 256>>>(x, XT);
    }
    prep_weights<<<PREP_TOTAL / 256, 256>>>(w_ih[0], w_ih[1], w_ih[2],
                                            w_hh[0], w_hh[1], w_hh[2]);

    const float* layin = XT;
    int Kin = INDIM;
    float* seqbuf[3] = {HA, HB, HA};

    for (int l = 0; l < 3; l++) {
        dim3 ggrid(G3 / 64, MROWS / 128);
        gemm_mma<<<ggrid, 256>>>(layin, WIH + (size_t)l * WSTRIDE, b_ih[l], XI, MROWS, G3, Kin);

        gru_layer<<<NCOLB * NROWB, 256>>>(XI, WHHP + (size_t)l * WHHP_L, b_hh[l],
                                          seqbuf[l], HP);

        layin = seqbuf[l];
        Kin = HH;
    }

    {
        const float* last = seqbuf[2] + (size_t)(TT - 1) * BB * HH;
        int warps = BB * PRED;
        int blocks = (warps * 32 + 255) / 256;
        fc_kernel<<<blocks, 256>>>(last, fcw, fcb, out);
    }
}